// round 7
// baseline (speedup 1.0000x reference)
#include <cuda_runtime.h>
#include <cuda_bf16.h>

#define FULLMASK 0xFFFFFFFFu
#define LOG2E 1.4426950408889634f

using u64 = unsigned long long;

__device__ __forceinline__ u64 fma2(u64 a, u64 b, u64 c) {
    u64 d; asm("fma.rn.f32x2 %0,%1,%2,%3;" : "=l"(d) : "l"(a), "l"(b), "l"(c)); return d;
}
__device__ __forceinline__ u64 bcast2(float v) {
    u64 d; asm("mov.b64 %0,{%1,%1};" : "=l"(d) : "f"(v)); return d;
}
__device__ __forceinline__ float2 unpk(u64 v) {
    float2 r; asm("mov.b64 {%0,%1},%2;" : "=f"(r.x), "=f"(r.y) : "l"(v)); return r;
}
__device__ __forceinline__ float ex2f(float x) {
    float r; asm("ex2.approx.f32 %0,%1;" : "=f"(r) : "f"(x)); return r;
}
__device__ __forceinline__ float rcpf(float x) {
    float r; asm("rcp.approx.f32 %0,%1;" : "=f"(r) : "f"(x)); return r;
}
__device__ __forceinline__ float rsqf(float x) {
    float r; asm("rsqrt.approx.f32 %0,%1;" : "=f"(r) : "f"(x)); return r;
}

union Row { ulonglong2 u; float4 f; };

// Layout: 4 locations per warp, 8 lanes per location.
// t = lane&7, h = t>>2 (row-half), q = t&3 (d-quad; quads = width-4 segments).
// Lane holds 8 rows of its half (i = 8h + r) in ROTATION ORDER:
//   slot (k,j), k=0..3, j=0..1  ->  local row r = 2*((q+k)&3) + j
// and columns d = 4q..4q+3 of each row.
//
// Each lane OWNS rows 8h+2q, 8h+2q+1 (its k=0 slots): it alone keeps their
// logits bb0/bb1 and computes their exponentials. Quad communication uses
// shfl.idx within width-4 segments:
//   e-gather:  slot (k,j) value comes from lane (q+k)&3 sending its own e_j.
//   agree ring-reduce: at step k, every lane sends its partial slot (4-k)&3
//   and the reader (q = sender-k) receives the partial for ITS OWN rows.
// All shfl register slots are compile-time; no dynamic indexing.
//
// b kept in log2-space; softmax normalizer 1/s never materialized (cancels in
// squash): out = a * sq * rcp(s^2+sq) * rsq(sq + eps*s^2). No max-subtract.
__global__ void __launch_bounds__(256) routing_kernel(
    const float* __restrict__ pred,
    const float* __restrict__ b_in,
    const int*   __restrict__ nit,
    float*       __restrict__ out,
    int n_loc, int ohw, int ohw_mask)
{
    const int lane = threadIdx.x & 31;
    const int t = lane & 7;
    const int h = t >> 2;
    const int q = t & 3;
    const unsigned warp_id = blockIdx.x * (blockDim.x >> 5) + (threadIdx.x >> 5);
    const int g = lane >> 3;
    if (warp_id * 4u >= (unsigned)n_loc) return;
    const unsigned loc = warp_id * 4u + g;

    // ring sources within the quad (explicit in-range indices for width=4)
    const int s1 = (q + 1) & 3, s2 = (q + 2) & 3, s3 = (q + 3) & 3;

    // ---- pred tile: 8 LDG.128, rotation-ordered rows ----
    const ulonglong2* p4 =
        reinterpret_cast<const ulonglong2*>(pred) + (size_t)warp_id * 256;
    Row P[8];
    {
        const int base = 64 * g + 32 * h + q;
#pragma unroll
        for (int k = 0; k < 4; ++k) {
            const int off = 8 * ((q + k) & 3);
            P[2 * k].u     = p4[base + off];
            P[2 * k + 1].u = p4[base + off + 4];
        }
    }

    // ---- logits for OWNED rows only: one LDG.64 (log2-space) ----
    const unsigned bloc = ohw_mask ? (loc & (unsigned)ohw_mask)
                                   : (loc % (unsigned)ohw);
    float bb0, bb1;
    {
        const float2 b2 = *reinterpret_cast<const float2*>(
            b_in + (size_t)bloc * 16 + 8 * h + 2 * q);
        bb0 = b2.x * LOG2E;
        bb1 = b2.y * LOG2E;
    }

    const int iters = *nit;
    float o0, o1, o2, o3;

    auto pass = [&]() {
        // exponentials of owned rows only, then quad-gather in slot order
        const float e0 = ex2f(bb0), e1 = ex2f(bb1);
        float e[8];
        e[0] = e0; e[1] = e1;
        e[2] = __shfl_sync(FULLMASK, e0, s1, 4);
        e[3] = __shfl_sync(FULLMASK, e1, s1, 4);
        e[4] = __shfl_sync(FULLMASK, e0, s2, 4);
        e[5] = __shfl_sync(FULLMASK, e1, s2, 4);
        e[6] = __shfl_sync(FULLMASK, e0, s3, 4);
        e[7] = __shfl_sync(FULLMASK, e1, s3, 4);

        float s = ((e[0] + e[1]) + (e[2] + e[3])) +
                  ((e[4] + e[5]) + (e[6] + e[7]));
        s += __shfl_xor_sync(FULLMASK, s, 4);    // other row-half

        // unnormalized weighted sum over this half's 8 rows (packed f32x2)
        u64 a01 = 0ull, a23 = 0ull;
#pragma unroll
        for (int r = 0; r < 8; ++r) {
            const u64 ee = bcast2(e[r]);
            a01 = fma2(ee, P[r].u.x, a01);
            a23 = fma2(ee, P[r].u.y, a23);
        }
        // add other half
        {
            u64 b01 = __shfl_xor_sync(FULLMASK, a01, 4);
            u64 b23 = __shfl_xor_sync(FULLMASK, a23, 4);
            a01 = fma2(bcast2(1.0f), b01, a01);
            a23 = fma2(bcast2(1.0f), b23, a23);
        }
        float2 lo = unpk(a01), hi = unpk(a23);
        const float a0 = lo.x, a1 = lo.y, a2 = hi.x, a3 = hi.y;

        // |a|^2 over all 16 d: local quad-cols + 2-step quad reduce
        float sq = fmaf(a3, a3, fmaf(a2, a2, fmaf(a1, a1, a0 * a0)));
        sq += __shfl_xor_sync(FULLMASK, sq, 1);
        sq += __shfl_xor_sync(FULLMASK, sq, 2);

        // folded squash (1/s cancelled)
        const float ssq = s * s;
        const float f   = sq * rcpf(ssq + sq) * rsqf(fmaf(1e-7f, ssq, sq));
        o0 = a0 * f; o1 = a1 * f; o2 = a2 * f; o3 = a3 * f;
    };

    pass();
    for (int it = 0; it < iters; ++it) {
        // local partial dots for all 8 slots (cols 4q..4q+3)
        float pp[8];
#pragma unroll
        for (int m = 0; m < 8; ++m)
            pp[m] = fmaf(P[m].f.w, o3,
                    fmaf(P[m].f.z, o2,
                    fmaf(P[m].f.y, o1, P[m].f.x * o0)));
        // ring reduce: own rows are slot k=0; partner at +k holds them in
        // slot (4-k)&3  (k=1 -> slot3 = pp[6,7]; k=2 -> slot2 = pp[4,5];
        //                k=3 -> slot1 = pp[2,3])
        float p0 = pp[0] + __shfl_sync(FULLMASK, pp[6], s1, 4);
        float p1 = pp[1] + __shfl_sync(FULLMASK, pp[7], s1, 4);
        p0 += __shfl_sync(FULLMASK, pp[4], s2, 4);
        p1 += __shfl_sync(FULLMASK, pp[5], s2, 4);
        p0 += __shfl_sync(FULLMASK, pp[2], s3, 4);
        p1 += __shfl_sync(FULLMASK, pp[3], s3, 4);

        bb0 = fmaf(p0, LOG2E, bb0);
        bb1 = fmaf(p1, LOG2E, bb1);
        pass();
    }

    if (h == 0)
        reinterpret_cast<float4*>(out)[(size_t)loc * 4 + q] =
            make_float4(o0, o1, o2, o3);
}

extern "C" void kernel_launch(void* const* d_in, const int* in_sizes, int n_in,
                              void* d_out, int out_size) {
    const float* pred = (const float*)d_in[0];
    const float* b    = (const float*)d_in[1];
    const int*   nit  = (const int*)d_in[2];
    float* out = (float*)d_out;

    const int n_loc = in_sizes[0] / 256;   // B*O*H*W
    const int ohw   = in_sizes[1] / 16;    // O*H*W
    const int ohw_mask = ((ohw & (ohw - 1)) == 0) ? (ohw - 1) : 0;

    const int warps  = (n_loc + 3) / 4;    // 4 locations per warp
    const int blocks = (warps + 7) / 8;    // 8 warps per block
    routing_kernel<<<blocks, 256>>>(pred, b, nit, out, n_loc, ohw, ohw_mask);
}